// round 1
// baseline (speedup 1.0000x reference)
#include <cuda_runtime.h>
#include <math.h>

#define BB   4
#define SS   2048
#define DD   1024
#define HH   16
#define HDIM 64
#define DFFN 4096
#define MM   (BB*SS)

// ------------------------- scratch (device globals; no allocs allowed) ------
__device__ float g_q[MM * DD];              // q, then tmp for Wo gemm out
__device__ float g_k[MM * DD];              // k, then attn_out (post LN1)
__device__ float g_v[MM * DD];              // v, then Wo2 gemm out
__device__ float g_ctx[MM * DD];            // attention context
__device__ float g_ffn[(size_t)MM * DFFN];  // gelu(Wi gemm) output

// ------------------------------ helpers ------------------------------------
__device__ __forceinline__ float gelu_f(float x) {
    return 0.5f * x * (1.0f + erff(x * 0.70710678118654752f));
}

// ------------------------------ GEMM ----------------------------------------
// C[M,N] = A[M,K] @ B[K,N] + bias[N]   (optional exact GELU)
// BM=BN=128, BK=8, 256 threads, 8x8 per-thread micro-tile.
__global__ __launch_bounds__(256, 2)
void gemm_bias_kernel(const float* __restrict__ A, const float* __restrict__ B,
                      const float* __restrict__ bias, float* __restrict__ C,
                      int M, int N, int K, int act) {
    __shared__ float As[8][128];
    __shared__ float Bs[8][128];

    const int tid  = threadIdx.x;
    const int brow = blockIdx.y << 7;
    const int bcol = blockIdx.x << 7;
    const int trow = (tid >> 4) << 3;   // 0..120
    const int tcol = (tid & 15) << 3;   // 0..120

    const int ar = tid >> 1;            // 0..127
    const int ac = (tid & 1) << 2;      // 0 or 4
    const int br = tid >> 5;            // 0..7
    const int bc = (tid & 31) << 2;     // 0..124

    const float* Aptr = A + (size_t)(brow + ar) * K + ac;
    const float* Bptr = B + (size_t)br * N + bcol + bc;

    float acc[8][8];
#pragma unroll
    for (int i = 0; i < 8; i++)
#pragma unroll
        for (int j = 0; j < 8; j++) acc[i][j] = 0.0f;

    for (int k0 = 0; k0 < K; k0 += 8) {
        const float4 av = *(const float4*)(Aptr + k0);
        const float4 bv = *(const float4*)(Bptr + (size_t)k0 * N);
        __syncthreads();   // previous tile's compute done
        As[ac + 0][ar] = av.x;
        As[ac + 1][ar] = av.y;
        As[ac + 2][ar] = av.z;
        As[ac + 3][ar] = av.w;
        *(float4*)&Bs[br][bc] = bv;
        __syncthreads();
#pragma unroll
        for (int kk = 0; kk < 8; ++kk) {
            float a[8], b[8];
            const float4 a0 = *(const float4*)&As[kk][trow];
            const float4 a1 = *(const float4*)&As[kk][trow + 4];
            const float4 b0 = *(const float4*)&Bs[kk][tcol];
            const float4 b1 = *(const float4*)&Bs[kk][tcol + 4];
            a[0]=a0.x; a[1]=a0.y; a[2]=a0.z; a[3]=a0.w;
            a[4]=a1.x; a[5]=a1.y; a[6]=a1.z; a[7]=a1.w;
            b[0]=b0.x; b[1]=b0.y; b[2]=b0.z; b[3]=b0.w;
            b[4]=b1.x; b[5]=b1.y; b[6]=b1.z; b[7]=b1.w;
#pragma unroll
            for (int i = 0; i < 8; i++)
#pragma unroll
                for (int j = 0; j < 8; j++) acc[i][j] += a[i] * b[j];
        }
    }

    const float4 bb0 = *(const float4*)&bias[bcol + tcol];
    const float4 bb1 = *(const float4*)&bias[bcol + tcol + 4];
    const float bvals[8] = {bb0.x, bb0.y, bb0.z, bb0.w, bb1.x, bb1.y, bb1.z, bb1.w};

#pragma unroll
    for (int i = 0; i < 8; i++) {
        const size_t row = (size_t)(brow + trow + i);
        float r[8];
#pragma unroll
        for (int j = 0; j < 8; j++) {
            float x = acc[i][j] + bvals[j];
            r[j] = act ? gelu_f(x) : x;
        }
        *(float4*)&C[row * N + bcol + tcol]     = make_float4(r[0], r[1], r[2], r[3]);
        *(float4*)&C[row * N + bcol + tcol + 4] = make_float4(r[4], r[5], r[6], r[7]);
    }
}

// ------------------------------ attention -----------------------------------
// Flash-style: one CTA handles 64 query rows of one (b,h); sweeps K in 64-row
// tiles with online softmax. 256 threads, each owns a 4x4 score/output tile.
// K tile stored with XOR-4 column swizzle for conflict-free LDS.128.
__global__ __launch_bounds__(256, 2)
void attn_kernel(const float* __restrict__ Q, const float* __restrict__ Kg,
                 const float* __restrict__ Vg, const float* __restrict__ mask,
                 float* __restrict__ O) {
    __shared__ float Qs[64][64];
    __shared__ float KP[64][64];   // K tile (swizzled), then reused for P
    __shared__ float Vs[64][64];

    const int tid = threadIdx.x;
    const int bh  = blockIdx.y;
    const int b   = bh >> 4;
    const int h   = bh & 15;
    const int q0  = blockIdx.x << 6;
    const int tx  = tid & 15;
    const int ty  = tid >> 4;

    // load Q tile, pre-scaled by 1/sqrt(64)
    for (int i = tid; i < 64 * 16; i += 256) {
        const int r = i >> 4;
        const int c = (i & 15) << 2;
        float4 qv = *(const float4*)&Q[(size_t)(b * SS + q0 + r) * DD + h * HDIM + c];
        qv.x *= 0.125f; qv.y *= 0.125f; qv.z *= 0.125f; qv.w *= 0.125f;
        *(float4*)&Qs[r][c] = qv;
    }

    float m_[4], l_[4], o_[4][4];
#pragma unroll
    for (int i = 0; i < 4; i++) {
        m_[i] = -3.0e38f;
        l_[i] = 0.0f;
#pragma unroll
        for (int j = 0; j < 4; j++) o_[i][j] = 0.0f;
    }

    for (int k0 = 0; k0 < SS; k0 += 64) {
        __syncthreads();   // protect KP/Vs reuse (also covers Qs visibility)
        for (int i = tid; i < 64 * 16; i += 256) {
            const int r = i >> 4;
            const int c = (i & 15) << 2;
            const size_t gidx = (size_t)(b * SS + k0 + r) * DD + h * HDIM + c;
            const float4 kv = *(const float4*)&Kg[gidx];
            const int sc = c ^ (((r >> 2) & 7) << 2);
            *(float4*)&KP[r][sc] = kv;
            *(float4*)&Vs[r][c]  = *(const float4*)&Vg[gidx];
        }
        __syncthreads();

        // scores: S = Q @ K^T (4x4 per thread)
        float s[4][4];
#pragma unroll
        for (int i = 0; i < 4; i++)
#pragma unroll
            for (int j = 0; j < 4; j++) s[i][j] = 0.0f;

        const int swz = (tx & 7) << 2;
#pragma unroll
        for (int kk = 0; kk < 64; kk += 4) {
            float4 qv[4], kv[4];
#pragma unroll
            for (int i = 0; i < 4; i++) qv[i] = *(const float4*)&Qs[4 * ty + i][kk];
            const int col = kk ^ swz;
#pragma unroll
            for (int j = 0; j < 4; j++) kv[j] = *(const float4*)&KP[4 * tx + j][col];
#pragma unroll
            for (int i = 0; i < 4; i++)
#pragma unroll
                for (int j = 0; j < 4; j++)
                    s[i][j] += qv[i].x * kv[j].x + qv[i].y * kv[j].y
                             + qv[i].z * kv[j].z + qv[i].w * kv[j].w;
        }

        // additive mask (broadcast over queries)
        const float4 mk = *(const float4*)&mask[b * SS + k0 + 4 * tx];
#pragma unroll
        for (int i = 0; i < 4; i++) {
            s[i][0] += mk.x; s[i][1] += mk.y; s[i][2] += mk.z; s[i][3] += mk.w;
        }

        // online softmax update (row groups of 16 lanes)
#pragma unroll
        for (int i = 0; i < 4; i++) {
            float rm = fmaxf(fmaxf(s[i][0], s[i][1]), fmaxf(s[i][2], s[i][3]));
#pragma unroll
            for (int off = 1; off < 16; off <<= 1)
                rm = fmaxf(rm, __shfl_xor_sync(0xffffffffu, rm, off));
            const float mn   = fmaxf(m_[i], rm);
            const float corr = __expf(m_[i] - mn);
            float rs = 0.0f;
#pragma unroll
            for (int j = 0; j < 4; j++) {
                s[i][j] = __expf(s[i][j] - mn);
                rs += s[i][j];
            }
#pragma unroll
            for (int off = 1; off < 16; off <<= 1)
                rs += __shfl_xor_sync(0xffffffffu, rs, off);
            l_[i] = l_[i] * corr + rs;
            m_[i] = mn;
#pragma unroll
            for (int j = 0; j < 4; j++) o_[i][j] *= corr;
        }

        __syncthreads();   // everyone done reading KP as K
#pragma unroll
        for (int i = 0; i < 4; i++)
#pragma unroll
            for (int j = 0; j < 4; j++) KP[4 * ty + i][4 * tx + j] = s[i][j];
        __syncthreads();

        // O += P @ V
#pragma unroll
        for (int kk = 0; kk < 64; kk += 4) {
            float4 pv[4], vv[4];
#pragma unroll
            for (int i = 0; i < 4; i++) pv[i] = *(const float4*)&KP[4 * ty + i][kk];
#pragma unroll
            for (int t = 0; t < 4; t++) vv[t] = *(const float4*)&Vs[kk + t][4 * tx];
#pragma unroll
            for (int i = 0; i < 4; i++) {
                o_[i][0] += pv[i].x * vv[0].x + pv[i].y * vv[1].x + pv[i].z * vv[2].x + pv[i].w * vv[3].x;
                o_[i][1] += pv[i].x * vv[0].y + pv[i].y * vv[1].y + pv[i].z * vv[2].y + pv[i].w * vv[3].y;
                o_[i][2] += pv[i].x * vv[0].z + pv[i].y * vv[1].z + pv[i].z * vv[2].z + pv[i].w * vv[3].z;
                o_[i][3] += pv[i].x * vv[0].w + pv[i].y * vv[1].w + pv[i].z * vv[2].w + pv[i].w * vv[3].w;
            }
        }
    }

#pragma unroll
    for (int i = 0; i < 4; i++) {
        const float inv = 1.0f / l_[i];
        const float4 res = make_float4(o_[i][0] * inv, o_[i][1] * inv,
                                       o_[i][2] * inv, o_[i][3] * inv);
        *(float4*)&O[(size_t)(b * SS + q0 + 4 * ty + i) * DD + h * HDIM + 4 * tx] = res;
    }
}

// ------------------------------ LayerNorm -----------------------------------
__device__ __forceinline__ float block_sum_256(float v) {
    __shared__ float red[8];
    const int lane = threadIdx.x & 31;
    const int w    = threadIdx.x >> 5;
#pragma unroll
    for (int off = 16; off; off >>= 1) v += __shfl_xor_sync(0xffffffffu, v, off);
    __syncthreads();                 // protect red across calls
    if (lane == 0) red[w] = v;
    __syncthreads();
    return red[0] + red[1] + red[2] + red[3] + red[4] + red[5] + red[6] + red[7];
}

// out = LayerNorm(Y + R) * g + b, per 1024-wide row, 256 threads (f4 each)
__global__ __launch_bounds__(256)
void ln_kernel(const float* __restrict__ Y, const float* __restrict__ R,
               const float* __restrict__ g, const float* __restrict__ bta,
               float* __restrict__ out) {
    const int row = blockIdx.x;
    const int tid = threadIdx.x;
    float4 v = ((const float4*)(Y + (size_t)row * DD))[tid];
    const float4 r = ((const float4*)(R + (size_t)row * DD))[tid];
    v.x += r.x; v.y += r.y; v.z += r.z; v.w += r.w;

    const float tot  = block_sum_256(v.x + v.y + v.z + v.w);
    const float mean = tot * (1.0f / 1024.0f);
    const float dx = v.x - mean, dy = v.y - mean, dz = v.z - mean, dw = v.w - mean;
    const float tot2 = block_sum_256(dx * dx + dy * dy + dz * dz + dw * dw);
    const float rstd = rsqrtf(tot2 * (1.0f / 1024.0f) + 1e-12f);

    const float4 gg = ((const float4*)g)[tid];
    const float4 bb = ((const float4*)bta)[tid];
    float4 o;
    o.x = dx * rstd * gg.x + bb.x;
    o.y = dy * rstd * gg.y + bb.y;
    o.z = dz * rstd * gg.z + bb.z;
    o.w = dw * rstd * gg.w + bb.w;
    ((float4*)(out + (size_t)row * DD))[tid] = o;
}

// ------------------------------ launch --------------------------------------
extern "C" void kernel_launch(void* const* d_in, const int* in_sizes, int n_in,
                              void* d_out, int out_size) {
    const float* x    = (const float*)d_in[0];
    const float* mask = (const float*)d_in[1];
    const float* Wq   = (const float*)d_in[2];
    const float* bq   = (const float*)d_in[3];
    const float* Wk   = (const float*)d_in[4];
    const float* bk   = (const float*)d_in[5];
    const float* Wv   = (const float*)d_in[6];
    const float* bv   = (const float*)d_in[7];
    const float* Wo   = (const float*)d_in[8];
    const float* bo   = (const float*)d_in[9];
    const float* ln1g = (const float*)d_in[10];
    const float* ln1b = (const float*)d_in[11];
    const float* Wi   = (const float*)d_in[12];
    const float* bi   = (const float*)d_in[13];
    const float* Wo2  = (const float*)d_in[14];
    const float* bo2  = (const float*)d_in[15];
    const float* ln2g = (const float*)d_in[16];
    const float* ln2b = (const float*)d_in[17];
    float* out = (float*)d_out;

    float *q, *k, *v, *ctx, *ffn;
    cudaGetSymbolAddress((void**)&q,   g_q);
    cudaGetSymbolAddress((void**)&k,   g_k);
    cudaGetSymbolAddress((void**)&v,   g_v);
    cudaGetSymbolAddress((void**)&ctx, g_ctx);
    cudaGetSymbolAddress((void**)&ffn, g_ffn);

    const dim3 blk(256);
    const dim3 gD(DD / 128, MM / 128);     // N=1024 gemms
    const dim3 gF(DFFN / 128, MM / 128);   // N=4096 gemm
    const dim3 gAtt(SS / 64, BB * HH);

    // QKV projections
    gemm_bias_kernel<<<gD, blk>>>(x, Wq, bq, q, MM, DD, DD, 0);
    gemm_bias_kernel<<<gD, blk>>>(x, Wk, bk, k, MM, DD, DD, 0);
    gemm_bias_kernel<<<gD, blk>>>(x, Wv, bv, v, MM, DD, DD, 0);

    // attention -> ctx
    attn_kernel<<<gAtt, blk>>>(q, k, v, mask, ctx);

    // ctx @ Wo + bo -> q (tmp); LN1(q + x) -> k (attn_out)
    gemm_bias_kernel<<<gD, blk>>>(ctx, Wo, bo, q, MM, DD, DD, 0);
    ln_kernel<<<MM, blk>>>(q, x, ln1g, ln1b, k);

    // FFN: gelu(attn_out @ Wi + bi) -> ffn ; ffn @ Wo2 + bo2 -> v (tmp)
    gemm_bias_kernel<<<gF, blk>>>(k, Wi, bi, ffn, MM, DFFN, DD, 1);
    gemm_bias_kernel<<<gD, blk>>>(ffn, Wo2, bo2, v, MM, DD, DFFN, 0);

    // LN2(v + attn_out) -> out
    ln_kernel<<<MM, blk>>>(v, k, ln2g, ln2b, out);
}